// round 13
// baseline (speedup 1.0000x reference)
#include <cuda_runtime.h>

// SE block, one persistent kernel, 152 blocks x 1024 threads.
//
// KEY IDEA: interleave the read stream (pooling) and the write stream (scale)
// chip-wide instead of running them as two serial phases. Work unit = GROUP of
// 8 contiguous planes (8192 planes = 1024 groups; 256 planes/batch => each
// group lies in exactly ONE batch, G>>5). Block bid owns G = bid + 152*g.
// Per block: for g: reduce(G(g)); scale(G(g-2)).  Chip-wide reduce progress is
// uniform across batches, so a group's batch is fully pooled ~2 steps before
// its scale runs -> short blocking wait. Scale re-reads are ~30MB behind the
// read front => guaranteed L2 hits. DRAM sees mixed reads+writes throughout.
//
// Sync: per-batch monotone counters. reduce(G): tid<8 write d_s + threadfence,
// barrier, tid0 atomicAdd(&cnt[batch], 8); target T = next multiple of 256
// above the returned count (= 256*(launch+1): replay-safe, never reset).
// scale waits (wrap-safe) for cnt[batch] >= T.

#define C        256
#define BOT      32
#define HW       3136
#define HW4      784
#define QF4      196                 // float4 per (plane-quarter)
#define NG_GLOB  1024
#define GRID     152
#define NTHREADS 1024
#define LAG      2

__device__ float d_s[8192];           // pooled means
__device__ unsigned d_cnt[32];        // per-batch counters (monotone, no reset)

__global__ void __launch_bounds__(NTHREADS, 1) se_fused_kernel(
    const float* __restrict__ x,
    const float* __restrict__ w1, const float* __restrict__ b1,
    const float* __restrict__ w2, const float* __restrict__ b2,
    float* __restrict__ out)
{
    const int tid  = threadIdx.x;
    const int warp = tid >> 5;
    const int lane = tid & 31;
    const int bid  = blockIdx.x;
    const int ng   = (NG_GLOB - bid + GRID - 1) / GRID;   // 7 (bid<112) or 6

    __shared__ float    sh_q[8][4];   // per-plane quarter sums
    __shared__ float    sh_h[BOT];    // hidden units of current batch
    __shared__ float    sh_g[8];      // gates of current scale group
    __shared__ unsigned sh_T[8];      // per-group counter targets

    const float4* __restrict__ x4 = reinterpret_cast<const float4*>(x);
    float4* __restrict__ o4 = reinterpret_cast<float4*>(out);

    const int pin = warp >> 2;        // plane-in-group 0..7
    const int qtr = warp & 3;         // quarter 0..3

    for (int g = 0; g < ng + LAG; ++g) {
        // ================= reduce group g =================
        if (g < ng) {
            const int G = bid + GRID * g;
            const float4* __restrict__ xp =
                x4 + (size_t)G * (8 * HW4) + pin * HW4 + qtr * QF4;
            // 196 = 6*32 + 4 : 6 unguarded + 1 predicated load, independent
            float4 v0 = __ldg(xp + lane);
            float4 v1 = __ldg(xp + lane + 32);
            float4 v2 = __ldg(xp + lane + 64);
            float4 v3 = __ldg(xp + lane + 96);
            float4 v4 = __ldg(xp + lane + 128);
            float4 v5 = __ldg(xp + lane + 160);
            float4 v6 = make_float4(0.f, 0.f, 0.f, 0.f);
            if (lane < 4) v6 = __ldg(xp + 192 + lane);
            float s0 = (v0.x + v0.y) + (v0.z + v0.w);
            float s1 = (v1.x + v1.y) + (v1.z + v1.w);
            float s2 = (v2.x + v2.y) + (v2.z + v2.w);
            float s3 = (v3.x + v3.y) + (v3.z + v3.w);
            s0 += (v4.x + v4.y) + (v4.z + v4.w);
            s1 += (v5.x + v5.y) + (v5.z + v5.w);
            s2 += (v6.x + v6.y) + (v6.z + v6.w);
            float acc = (s0 + s1) + (s2 + s3);
            #pragma unroll
            for (int o = 16; o > 0; o >>= 1)
                acc += __shfl_xor_sync(0xffffffffu, acc, o);
            if (lane == 0) sh_q[pin][qtr] = acc;
            __syncthreads();
            if (tid < 8) {
                const float s = (sh_q[tid][0] + sh_q[tid][1])
                              + (sh_q[tid][2] + sh_q[tid][3]);
                d_s[G * 8 + tid] = s * (1.0f / (float)HW);
                __threadfence();      // publish before the counter bump
            }
            __syncthreads();
            if (tid == 0) {
                const unsigned c = atomicAdd(&d_cnt[G >> 5], 8u) + 8u;
                sh_T[g] = (c + 255u) & ~255u;   // = 256*(launch+1)
            }
        }

        // ================= scale group g-LAG =================
        const int sg = g - LAG;
        if (sg >= 0 && sg < ng) {
            const int G = bid + GRID * sg;
            const int b = G >> 5;
            if (tid == 0) {
                volatile unsigned* vc = d_cnt + b;
                const unsigned T = sh_T[sg];
                while ((int)(*vc - T) < 0) __nanosleep(64);
                __threadfence();      // acquire
            }
            __syncthreads();

            // hidden units of batch b: warp w -> unit w
            {
                const float* __restrict__ srow = d_s + b * C;
                const float* __restrict__ wrow = w1 + warp * C;
                float acc = 0.0f;
                #pragma unroll
                for (int k = 0; k < 8; k++) {
                    const int c2 = lane + 32 * k;
                    acc = fmaf(__ldg(srow + c2), __ldg(wrow + c2), acc);
                }
                #pragma unroll
                for (int o = 16; o > 0; o >>= 1)
                    acc += __shfl_xor_sync(0xffffffffu, acc, o);
                if (lane == 0)
                    sh_h[warp] = fmaxf(acc + __ldg(b1 + warp), 0.0f);
            }
            __syncthreads();

            if (tid < 8) {            // gates for the 8 planes of this group
                const int plane = G * 8 + tid;
                const int c2 = plane & 255;
                const float* __restrict__ wrow = w2 + c2 * BOT;
                float a = __ldg(b2 + c2);
                #pragma unroll
                for (int o = 0; o < BOT; o++)
                    a = fmaf(sh_h[o], __ldg(wrow + o), a);
                sh_g[tid] = 1.0f / (1.0f + __expf(-a));
            }
            __syncthreads();

            const float gg = sh_g[pin];        // warp-uniform gate
            const size_t base = (size_t)G * (8 * HW4) + pin * HW4 + qtr * QF4;
            const float4* __restrict__ xp = x4 + base;
            float4* __restrict__ op = o4 + base;
            float4 v0 = __ldcs(xp + lane);
            float4 v1 = __ldcs(xp + lane + 32);
            float4 v2 = __ldcs(xp + lane + 64);
            float4 v3 = __ldcs(xp + lane + 96);
            float4 v4 = __ldcs(xp + lane + 128);
            float4 v5 = __ldcs(xp + lane + 160);
            float4 v6 = make_float4(0.f, 0.f, 0.f, 0.f);
            const bool p6 = (lane < 4);
            if (p6) v6 = __ldcs(xp + 192 + lane);
            v0.x *= gg; v0.y *= gg; v0.z *= gg; v0.w *= gg;
            v1.x *= gg; v1.y *= gg; v1.z *= gg; v1.w *= gg;
            v2.x *= gg; v2.y *= gg; v2.z *= gg; v2.w *= gg;
            v3.x *= gg; v3.y *= gg; v3.z *= gg; v3.w *= gg;
            v4.x *= gg; v4.y *= gg; v4.z *= gg; v4.w *= gg;
            v5.x *= gg; v5.y *= gg; v5.z *= gg; v5.w *= gg;
            v6.x *= gg; v6.y *= gg; v6.z *= gg; v6.w *= gg;
            __stcs(op + lane,       v0);
            __stcs(op + lane + 32,  v1);
            __stcs(op + lane + 64,  v2);
            __stcs(op + lane + 96,  v3);
            __stcs(op + lane + 128, v4);
            __stcs(op + lane + 160, v5);
            if (p6) __stcs(op + 192 + lane, v6);
        }
    }
}

extern "C" void kernel_launch(void* const* d_in, const int* in_sizes, int n_in,
                              void* d_out, int out_size) {
    const float* x  = (const float*)d_in[0];
    const float* w1 = (const float*)d_in[1];
    const float* b1 = (const float*)d_in[2];
    const float* w2 = (const float*)d_in[3];
    const float* b2 = (const float*)d_in[4];
    float* out = (float*)d_out;

    se_fused_kernel<<<GRID, NTHREADS>>>(x, w1, b1, w2, b2, out);
}

// round 14
// speedup vs baseline: 1.1591x; 1.1591x over previous
#include <cuda_runtime.h>

// SE block, one persistent kernel, 152 blocks (one per GB300 SM).
// == R9 structure (best: 47.6us) with ONE change: phase-3 stores are plain
// writeback (not __stcs). out (103MB) < L2 (126MB): most dirty lines stay in
// L2 at kernel end and flush during the NEXT replay's read phase -> read and
// write DRAM streams interleave ACROSS graph replays with zero intra-kernel
// sync cost (the failure mode of R6/R12/R13).
//
// Phase 1: quarter-plane units (98 float8), 256-bit evict_last loads
//          (pins x in L2). Per-batch arrival counters (replay-safe mod-256).
// Phase 3: REVERSE streaming of the same chunk, __ldcs reads, writeback stores.

#define C        256
#define BOT      32
#define HW       3136
#define HW4      784
#define QP8      98                  // float8 per quarter-plane unit
#define BC       8192
#define GRID     152
#define NTHREADS 1024

__device__ float d_s[BC];                 // pooled means
__device__ unsigned int d_cnt[32];        // per-batch counters (never reset)

struct __align__(32) F8 { float4 a, b; };

__device__ __forceinline__ float ld8_el_sum(const F8* p) {
    unsigned r0, r1, r2, r3, r4, r5, r6, r7;
    asm volatile(
        "ld.global.nc.L2::evict_last.v8.b32 {%0,%1,%2,%3,%4,%5,%6,%7}, [%8];"
        : "=r"(r0), "=r"(r1), "=r"(r2), "=r"(r3),
          "=r"(r4), "=r"(r5), "=r"(r6), "=r"(r7)
        : "l"(p));
    float s0 = __uint_as_float(r0) + __uint_as_float(r1);
    float s1 = __uint_as_float(r2) + __uint_as_float(r3);
    float s2 = __uint_as_float(r4) + __uint_as_float(r5);
    float s3 = __uint_as_float(r6) + __uint_as_float(r7);
    return (s0 + s1) + (s2 + s3);
}

__global__ void __launch_bounds__(NTHREADS, 1) se_fused_kernel(
    const float* __restrict__ x,
    const float* __restrict__ w1, const float* __restrict__ b1,
    const float* __restrict__ w2, const float* __restrict__ b2,
    float* __restrict__ out)
{
    const int tid  = threadIdx.x;
    const int warp = tid >> 5;
    const int lane = tid & 31;
    const int bid  = blockIdx.x;

    const int p0 = (int)(((long long)bid * BC) / GRID);
    const int p1 = (int)(((long long)(bid + 1) * BC) / GRID);
    const int nk = p1 - p0;                  // 53 or 54 planes
    const int nu = nk * 4;                   // quarter-plane units (212/216)

    const int b0 = p0 >> 8;
    const int nb = ((p1 - 1) >> 8) - b0 + 1; // 1 or 2 batches touched
    const int n0 = min((b0 + 1) * C, p1) - p0;   // planes in batch b0
    const int n1 = nk - n0;                      // planes in batch b0+1

    __shared__ float sh_part[216];
    __shared__ float sh_s[2][C];
    __shared__ float sh_h[2][BOT];
    __shared__ float sh_g[64];

    // ------------- Phase 1: quarter-plane sums via 256-bit evict_last ---------
    const F8* __restrict__ xb8 =
        reinterpret_cast<const F8*>(x + (size_t)p0 * HW);
    for (int u = warp; u < nu; u += 32) {
        const F8* __restrict__ xp = xb8 + (size_t)u * QP8;
        // 98 = 3*32 + 2 : 3 unguarded + 1 predicated 32B load
        float s0 = ld8_el_sum(xp + lane);
        float s1 = ld8_el_sum(xp + lane + 32);
        float s2 = ld8_el_sum(xp + lane + 64);
        float s3 = (lane < 2) ? ld8_el_sum(xp + 96 + lane) : 0.0f;
        float sum = (s0 + s1) + (s2 + s3);
        #pragma unroll
        for (int o = 16; o > 0; o >>= 1)
            sum += __shfl_xor_sync(0xffffffffu, sum, o);
        if (lane == 0) sh_part[u] = sum;
    }
    __syncthreads();
    if (tid < nk) {
        const float* __restrict__ pp = sh_part + 4 * tid;
        d_s[p0 + tid] = ((pp[0] + pp[1]) + (pp[2] + pp[3])) * (1.0f / (float)HW);
    }
    __threadfence();                          // publish this thread's d_s write
    __syncthreads();

    // ------------- Per-batch arrive + wait (replay-safe, mod-256) -------------
    if (tid == 0) {
        atomicAdd(&d_cnt[b0], (unsigned)n0);
        if (n1 > 0) atomicAdd(&d_cnt[b0 + 1], (unsigned)n1);
        volatile unsigned int* vc = d_cnt;
        while (vc[b0] & 255u) __nanosleep(32);
        if (n1 > 0)
            while (vc[b0 + 1] & 255u) __nanosleep(32);
        __threadfence();
    }
    __syncthreads();

    // ---------------- Phase 2: means -> hidden -> gates for our chunk ---------
    for (int idx = tid; idx < nb * C; idx += NTHREADS)
        sh_s[idx >> 8][idx & 255] = d_s[b0 * C + idx];
    __syncthreads();

    for (int j = warp; j < nb * BOT; j += 32) {
        const int bi = j >> 5, o = j & 31;
        const float* __restrict__ w1row = w1 + o * C;
        float acc = 0.0f;
        #pragma unroll
        for (int k = 0; k < 8; k++) {
            const int c = lane + 32 * k;
            acc = fmaf(sh_s[bi][c], __ldg(w1row + c), acc);
        }
        #pragma unroll
        for (int off = 16; off > 0; off >>= 1)
            acc += __shfl_xor_sync(0xffffffffu, acc, off);
        if (lane == 0) sh_h[bi][o] = fmaxf(acc + __ldg(b1 + o), 0.0f);
    }
    __syncthreads();

    if (tid < nk) {
        const int plane = p0 + tid;
        const int c = plane & 255;
        const int bi = (plane >> 8) - b0;
        const float* __restrict__ wrow = w2 + c * BOT;
        float acc = __ldg(b2 + c);
        #pragma unroll
        for (int o = 0; o < BOT; o++)
            acc = fmaf(sh_h[bi][o], __ldg(wrow + o), acc);
        sh_g[tid] = 1.0f / (1.0f + __expf(-acc));
    }
    __syncthreads();

    // ---------------- Phase 3: REVERSE streaming, writeback stores ------------
    const unsigned int total = (unsigned int)nk * HW4;       // <= 42336
    const int nfull = (int)(total / (8u * NTHREADS));        // full 8-wide iters
    const float4* __restrict__ x4 =
        reinterpret_cast<const float4*>(x) + (size_t)p0 * HW4;
    float4* __restrict__ o4 = reinterpret_cast<float4*>(out) + (size_t)p0 * HW4;

    // tail first (highest addresses = hottest in L1/L2)
    for (unsigned int i = (unsigned int)nfull * 8u * NTHREADS + tid; i < total;
         i += NTHREADS) {
        const float g = sh_g[i / HW4];
        float4 v = __ldcs(x4 + i);
        v.x *= g; v.y *= g; v.z *= g; v.w *= g;
        o4[i] = v;
    }
    for (int it = nfull - 1; it >= 0; --it) {
        const unsigned int i = (unsigned int)it * 8u * NTHREADS + tid;
        float4 v0 = __ldcs(x4 + i);
        float4 v1 = __ldcs(x4 + i + 1 * NTHREADS);
        float4 v2 = __ldcs(x4 + i + 2 * NTHREADS);
        float4 v3 = __ldcs(x4 + i + 3 * NTHREADS);
        float4 v4 = __ldcs(x4 + i + 4 * NTHREADS);
        float4 v5 = __ldcs(x4 + i + 5 * NTHREADS);
        float4 v6 = __ldcs(x4 + i + 6 * NTHREADS);
        float4 v7 = __ldcs(x4 + i + 7 * NTHREADS);
        const float g0 = sh_g[(i) / HW4];
        const float g1 = sh_g[(i + 1 * NTHREADS) / HW4];
        const float g2 = sh_g[(i + 2 * NTHREADS) / HW4];
        const float g3 = sh_g[(i + 3 * NTHREADS) / HW4];
        const float g4 = sh_g[(i + 4 * NTHREADS) / HW4];
        const float g5 = sh_g[(i + 5 * NTHREADS) / HW4];
        const float g6 = sh_g[(i + 6 * NTHREADS) / HW4];
        const float g7 = sh_g[(i + 7 * NTHREADS) / HW4];
        v0.x *= g0; v0.y *= g0; v0.z *= g0; v0.w *= g0;
        v1.x *= g1; v1.y *= g1; v1.z *= g1; v1.w *= g1;
        v2.x *= g2; v2.y *= g2; v2.z *= g2; v2.w *= g2;
        v3.x *= g3; v3.y *= g3; v3.z *= g3; v3.w *= g3;
        v4.x *= g4; v4.y *= g4; v4.z *= g4; v4.w *= g4;
        v5.x *= g5; v5.y *= g5; v5.z *= g5; v5.w *= g5;
        v6.x *= g6; v6.y *= g6; v6.z *= g6; v6.w *= g6;
        v7.x *= g7; v7.y *= g7; v7.z *= g7; v7.w *= g7;
        o4[i]                = v0;
        o4[i + 1 * NTHREADS] = v1;
        o4[i + 2 * NTHREADS] = v2;
        o4[i + 3 * NTHREADS] = v3;
        o4[i + 4 * NTHREADS] = v4;
        o4[i + 5 * NTHREADS] = v5;
        o4[i + 6 * NTHREADS] = v6;
        o4[i + 7 * NTHREADS] = v7;
    }
}

extern "C" void kernel_launch(void* const* d_in, const int* in_sizes, int n_in,
                              void* d_out, int out_size) {
    const float* x  = (const float*)d_in[0];
    const float* w1 = (const float*)d_in[1];
    const float* b1 = (const float*)d_in[2];
    const float* w2 = (const float*)d_in[3];
    const float* b2 = (const float*)d_in[4];
    float* out = (float*)d_out;

    se_fused_kernel<<<GRID, NTHREADS>>>(x, w1, b1, w2, b2, out);
}